// round 12
// baseline (speedup 1.0000x reference)
#include <cuda_runtime.h>
#include <cstdint>

// Problem constants
#define LEN_M   1088
#define MPRI    65
#define NSAMP   100
#define NROWS   16384
#define DD1     17
#define DH      64
#define OUT_PRED ((size_t)NROWS * NSAMP * NSAMP)

typedef unsigned long long u64;
typedef uint32_t u32;

// ---------------- device globals (scratch; no allocation allowed) ------------
__device__ float g_W0T[NSAMP * LEN_M];            // [m][j], j=k*64+h  (fp32)
__device__ float g_w1[MPRI * NSAMP];              // [d][c]            (fp32)
// bf16 hi/lo operand images (ldmatrix rows, padded strides, 16B aligned):
__device__ __align__(16) u32 g_ximgH[NROWS * 12];   // [n][16k], 48B stride
__device__ __align__(16) u32 g_ximgL[NROWS * 12];
__device__ __align__(16) u32 g_w0imgH[NSAMP * 64 * 12];  // [m][h][16k], 48B
__device__ __align__(16) u32 g_w0imgL[NSAMP * 64 * 12];
__device__ __align__(16) u32 g_w1imgH[104 * 36];    // [c][64k pad 72], 144B
__device__ __align__(16) u32 g_w1imgL[104 * 36];
__device__ __align__(16) float g_x16[NROWS];        // x[:,16] packed fp32
__device__ __align__(16) float g_w0k16[NSAMP * 64]; // W0[16][h] per m, fp32

// ---------------- Threefry2x32 (exact JAX rotation/key schedule) -------------
__host__ __device__ inline void threefry(u32 k0, u32 k1, u32 c0, u32 c1,
                                         u32& o0, u32& o1) {
    u32 ks2 = k0 ^ k1 ^ 0x1BD11BDAu;
    u32 x0 = c0 + k0, x1 = c1 + k1;
#define TF_ROUND(r) { x0 += x1; x1 = (x1 << (r)) | (x1 >> (32 - (r))); x1 ^= x0; }
    TF_ROUND(13) TF_ROUND(15) TF_ROUND(26) TF_ROUND(6)
    x0 += k1;  x1 += ks2 + 1u;
    TF_ROUND(17) TF_ROUND(29) TF_ROUND(16) TF_ROUND(24)
    x0 += ks2; x1 += k0 + 2u;
    TF_ROUND(13) TF_ROUND(15) TF_ROUND(26) TF_ROUND(6)
    x0 += k0;  x1 += k1 + 3u;
    TF_ROUND(17) TF_ROUND(29) TF_ROUND(16) TF_ROUND(24)
    x0 += k1;  x1 += ks2 + 4u;
    TF_ROUND(13) TF_ROUND(15) TF_ROUND(26) TF_ROUND(6)
    x0 += ks2; x1 += k0 + 5u;
#undef TF_ROUND
    o0 = x0; o1 = x1;
}

__device__ inline float erfinv_xla(float x) {
    float w = -log1pf(-x * x);
    float p;
    if (w < 5.0f) {
        w -= 2.5f;
        p = 2.81022636e-08f;
        p = fmaf(p, w, 3.43273939e-07f);
        p = fmaf(p, w, -3.5233877e-06f);
        p = fmaf(p, w, -4.39150654e-06f);
        p = fmaf(p, w, 0.00021858087f);
        p = fmaf(p, w, -0.00125372503f);
        p = fmaf(p, w, -0.00417768164f);
        p = fmaf(p, w, 0.246640727f);
        p = fmaf(p, w, 1.50140941f);
    } else {
        w = sqrtf(w) - 3.0f;
        p = -0.000200214257f;
        p = fmaf(p, w, 0.000100950558f);
        p = fmaf(p, w, 0.00134934322f);
        p = fmaf(p, w, -0.00367342844f);
        p = fmaf(p, w, 0.00573950773f);
        p = fmaf(p, w, -0.0076224613f);
        p = fmaf(p, w, 0.00943887047f);
        p = fmaf(p, w, 1.00167406f);
        p = fmaf(p, w, 2.83297682f);
    }
    return p * x;
}

__device__ inline float bits_to_normal(u32 bits) {
    float f = __uint_as_float((bits >> 9) | 0x3f800000u) - 1.0f;
    const float lo = -0.99999994f;
    float u = __fadd_rn(__fmul_rn(f, 2.0f), lo);
    u = fmaxf(lo, u);
    return 1.4142135381698608f * erfinv_xla(u);
}

// ---------------- setup1: sample weights (fp32) + output tail ----------------
#define E0 108800
#define E1 6500
#define TAILN 2306

__global__ void setup1_kernel(const float* __restrict__ ms_vs,
                              float* __restrict__ out_tail,
                              u32 k0a, u32 k0b, u32 k1a, u32 k1b) {
    int t = blockIdx.x * blockDim.x + threadIdx.x;
    if (t < E0) {
        u32 o0, o1;
        threefry(k0a, k0b, 0u, (u32)t, o0, o1);
        float n = bits_to_normal(o0 ^ o1);
        int j = t / 100, m = t - j * 100;
        float v = fabsf(ms_vs[1153 + j]) + 1e-6f;
        g_W0T[m * LEN_M + j] = fmaf(n, sqrtf(v), ms_vs[j]);
    } else if (t < E0 + E1) {
        int i = t - E0;
        u32 o0, o1;
        threefry(k1a, k1b, 0u, (u32)i, o0, o1);
        float n = bits_to_normal(o0 ^ o1);
        int d = i / 100, c = i - d * 100;
        float v = fabsf(ms_vs[2241 + d]) + 1e-6f;
        g_w1[d * 100 + c] = fmaf(n, sqrtf(v), ms_vs[1088 + d]);
    } else if (t < E0 + E1 + TAILN) {
        int q = t - E0 - E1;
        float val;
        if (q < 1088)       val = ms_vs[q];
        else if (q < 2176)  val = fabsf(ms_vs[1153 + (q - 1088)]) + 1e-6f;
        else if (q < 2241)  val = ms_vs[1088 + (q - 2176)];
        else                val = fabsf(ms_vs[q]) + 1e-6f;
        out_tail[q] = val;
    }
}

// ---------------- setup2: build bf16 hi/lo operand images --------------------
__device__ inline void bf16split2(float a, float b, u32& H, u32& L) {
    asm("cvt.rn.bf16x2.f32 %0, %1, %2;" : "=r"(H) : "f"(b), "f"(a));  // lo half = a
    float hf0 = __uint_as_float(H << 16);
    float hf1 = __uint_as_float(H & 0xFFFF0000u);
    float l0 = a - hf0, l1 = b - hf1;
    asm("cvt.rn.bf16x2.f32 %0, %1, %2;" : "=r"(L) : "f"(l1), "f"(l0));
}

#define SX  131072   // X slots: 16384*8
#define SX1 16384    // x16
#define SW0 51200    // 100*64*8
#define SWK 6400     // w0k16
#define SW1 3744     // 104*36
#define S2TOT (SX + SX1 + SW0 + SWK + SW1)

__global__ void setup2_kernel(const float* __restrict__ x) {
    int s = blockIdx.x * blockDim.x + threadIdx.x;
    if (s < SX) {
        int n = s >> 3, p = s & 7;
        int k = 2 * p;
        float a = x[n * DD1 + k];
        float b = x[n * DD1 + k + 1];
        u32 H, L; bf16split2(a, b, H, L);
        g_ximgH[n * 12 + p] = H;
        g_ximgL[n * 12 + p] = L;
    } else if (s < SX + SX1) {
        int n = s - SX;
        g_x16[n] = x[n * DD1 + 16];
    } else if (s < SX + SX1 + SW0) {
        int r = s - SX - SX1;
        int m = r >> 9, t = r & 511;
        int h = t >> 3, p = t & 7;
        int k = 2 * p;
        float a = g_W0T[m * LEN_M + k * DH + h];
        float b = g_W0T[m * LEN_M + (k + 1) * DH + h];
        u32 H, L; bf16split2(a, b, H, L);
        g_w0imgH[(m * 64 + h) * 12 + p] = H;
        g_w0imgL[(m * 64 + h) * 12 + p] = L;
    } else if (s < SX + SX1 + SW0 + SWK) {
        int r = s - SX - SX1 - SW0;
        int m = r >> 6, h = r & 63;
        g_w0k16[r] = g_W0T[m * LEN_M + 16 * DH + h];
    } else if (s < S2TOT) {
        int r = s - SX - SX1 - SW0 - SWK;
        int c = r / 36, p = r - c * 36;
        int k = 2 * p;                            // K idx -> w1 row d=k+1
        float a = (k     < 64 && c < 100) ? g_w1[(k + 1) * 100 + c] : 0.0f;
        float b = (k + 1 < 64 && c < 100) ? g_w1[(k + 2) * 100 + c] : 0.0f;
        u32 H, L; bf16split2(a, b, H, L);
        g_w1imgH[r] = H;
        g_w1imgL[r] = L;
    }
}

// ---------------- mma.sync / ldmatrix / mbarrier helpers ---------------------
__device__ __forceinline__ void ldx4(u32* r, u32 addr) {
    asm volatile("ldmatrix.sync.aligned.m8n8.x4.shared.b16 {%0,%1,%2,%3}, [%4];"
                 : "=r"(r[0]), "=r"(r[1]), "=r"(r[2]), "=r"(r[3]) : "r"(addr));
}
__device__ __forceinline__ void ldx2(u32* r, u32 addr) {
    asm volatile("ldmatrix.sync.aligned.m8n8.x2.shared.b16 {%0,%1}, [%2];"
                 : "=r"(r[0]), "=r"(r[1]) : "r"(addr));
}
__device__ __forceinline__ void mma16816(float* d, const u32* a, const u32* b) {
    asm volatile("mma.sync.aligned.m16n8k16.row.col.f32.bf16.bf16.f32 "
                 "{%0,%1,%2,%3}, {%4,%5,%6,%7}, {%8,%9}, {%0,%1,%2,%3};"
                 : "+f"(d[0]), "+f"(d[1]), "+f"(d[2]), "+f"(d[3])
                 : "r"(a[0]), "r"(a[1]), "r"(a[2]), "r"(a[3]), "r"(b[0]), "r"(b[1]));
}
#define MBAR_INIT(a, n)   asm volatile("mbarrier.init.shared.b64 [%0], %1;" :: "r"(a), "r"((u32)(n)) : "memory")
#define MBAR_EXPECT(a, b) asm volatile("mbarrier.arrive.expect_tx.shared.b64 _, [%0], %1;" :: "r"(a), "r"((u32)(b)) : "memory")
__device__ __forceinline__ void mbar_wait(u32 addr, u32 parity) {
    asm volatile("{\n\t.reg .pred P1;\n\t"
        "WAIT_LOOP_%=:\n\t"
        "mbarrier.try_wait.parity.acquire.cta.shared::cta.b64 P1, [%0], %1, 0x989680;\n\t"
        "@P1 bra.uni WAIT_DONE_%=;\n\t"
        "bra.uni WAIT_LOOP_%=;\n\t"
        "WAIT_DONE_%=:\n\t}"
        :: "r"(addr), "r"(parity) : "memory");
}
__device__ __forceinline__ void bulk_cp(u32 dst_smem, const void* src, u32 bytes, u32 mbar) {
    asm volatile("cp.async.bulk.shared::cluster.global.mbarrier::complete_tx::bytes "
                 "[%0], [%1], %2, [%3];"
                 :: "r"(dst_smem), "l"(src), "r"(bytes), "r"(mbar) : "memory");
}

// ---------------- pred kernel ------------------------------------------------
// smem (bytes):
#define SM_XH   1024     // [128][48B] = 6144
#define SM_XL   7168     // 6144
#define SM_W0H  13312    // [64][48B] = 3072
#define SM_W0L  16384    // 3072
#define SM_W1H  19456    // [104][144B] = 14976
#define SM_W1L  34432    // 14976
#define SM_X16  49408    // 512
#define SM_W0K  49920    // 256
#define SM_BS   50176    // 416 (400 copied)
#define SM_ZH   50592    // [128][144B] = 18432
#define SM_ZL   69024    // 18432
#define SM_BYTES 87552
#define FILL_BYTES 49552u

__global__ void __launch_bounds__(256, 2) pred_kernel(float* __restrict__ out) {
    extern __shared__ char sm[];
    u32 sb;
    asm("{ .reg .u64 t; cvta.to.shared.u64 t, %1; cvt.u32.u64 %0, t; }"
        : "=r"(sb) : "l"(sm));

    const int tid  = threadIdx.x;
    const int lane = tid & 31;
    const int w    = tid >> 5;              // 0..7: n-strip rows 16w..16w+15
    const int m    = blockIdx.y;
    const int n0   = blockIdx.x * 128;

    if (tid == 0) {
        MBAR_INIT(sb + 8, 1);
        MBAR_EXPECT(sb + 8, FILL_BYTES);
        bulk_cp(sb + SM_XH,  g_ximgH  + (size_t)n0 * 12, 6144u, sb + 8);
        bulk_cp(sb + SM_XL,  g_ximgL  + (size_t)n0 * 12, 6144u, sb + 8);
        bulk_cp(sb + SM_W0H, g_w0imgH + (size_t)m * 768, 3072u, sb + 8);
        bulk_cp(sb + SM_W0L, g_w0imgL + (size_t)m * 768, 3072u, sb + 8);
        bulk_cp(sb + SM_W1H, g_w1imgH, 14976u, sb + 8);
        bulk_cp(sb + SM_W1L, g_w1imgL, 14976u, sb + 8);
        bulk_cp(sb + SM_X16, g_x16 + n0, 512u, sb + 8);
        bulk_cp(sb + SM_W0K, g_w0k16 + m * 64, 256u, sb + 8);
        bulk_cp(sb + SM_BS,  g_w1, 400u, sb + 8);
    }
    __syncthreads();
    mbar_wait(sb + 8, 0);

    // ---- GEMM1: D1[16 rows x 64 h] per warp; K=16, 3-product split ----
    float acc1[8][4];
#pragma unroll
    for (int t = 0; t < 8; ++t)
#pragma unroll
        for (int j = 0; j < 4; ++j) acc1[t][j] = 0.0f;

    {
        u32 Ah[4], Al[4];
        ldx4(Ah, sb + SM_XH + (16 * w + (lane & 15)) * 48 + (lane >> 4) * 16);
        ldx4(Al, sb + SM_XL + (16 * w + (lane & 15)) * 48 + (lane >> 4) * 16);
        const u32 bB = (lane & 7) * 48 + ((lane >> 3) & 1) * 16;
#pragma unroll
        for (int t = 0; t < 8; ++t) {
            u32 Bh[2], Bl[2];
            ldx2(Bh, sb + SM_W0H + t * 384 + bB);
            ldx2(Bl, sb + SM_W0L + t * 384 + bB);
            mma16816(acc1[t], Ah, Bh);
            mma16816(acc1[t], Ah, Bl);
            mma16816(acc1[t], Al, Bh);
        }
    }

    // ---- epi1: + exact fp32 k=16 term, relu, bf16 split -> Zh/Zl smem ----
    {
        const int r0 = 16 * w + (lane >> 2);
        const int cb = 2 * (lane & 3);
        const float* x16s = (const float*)(sm + SM_X16);
        const float* w0ks = (const float*)(sm + SM_W0K);
        const float xa = x16s[r0], xb = x16s[r0 + 8];
#pragma unroll
        for (int t = 0; t < 8; ++t) {
            const float wa = w0ks[8 * t + cb], wb = w0ks[8 * t + cb + 1];
            u32 H, L;
            float z0 = fmaxf(fmaf(xa, wa, acc1[t][0]), 0.0f);
            float z1 = fmaxf(fmaf(xa, wb, acc1[t][1]), 0.0f);
            bf16split2(z0, z1, H, L);
            u32 off = r0 * 144 + (8 * t + cb) * 2;
            *(u32*)(sm + SM_ZH + off) = H;
            *(u32*)(sm + SM_ZL + off) = L;
            float z2 = fmaxf(fmaf(xb, wa, acc1[t][2]), 0.0f);
            float z3 = fmaxf(fmaf(xb, wb, acc1[t][3]), 0.0f);
            bf16split2(z2, z3, H, L);
            off += 8 * 144;
            *(u32*)(sm + SM_ZH + off) = H;
            *(u32*)(sm + SM_ZL + off) = L;
        }
    }
    __syncthreads();

    // ---- GEMM2: D2[16 rows x 104 c] per warp; K=64; bias preloaded ----
    float acc[13][4];
    {
        const int cb = 2 * (lane & 3);
        const float* bs = (const float*)(sm + SM_BS);
#pragma unroll
        for (int t = 0; t < 13; ++t) {
            float b0 = bs[8 * t + cb], b1 = bs[8 * t + cb + 1];
            acc[t][0] = b0; acc[t][1] = b1; acc[t][2] = b0; acc[t][3] = b1;
        }
    }
    {
        const u32 aH = sb + SM_ZH + (16 * w + (lane & 15)) * 144 + (lane >> 4) * 16;
        const u32 aL = sb + SM_ZL + (16 * w + (lane & 15)) * 144 + (lane >> 4) * 16;
        const u32 bB = (lane & 7) * 144 + ((lane >> 3) & 1) * 16;
#pragma unroll
        for (int ks = 0; ks < 4; ++ks) {
            u32 Ah[4], Al[4];
            ldx4(Ah, aH + ks * 32);
            ldx4(Al, aL + ks * 32);
#pragma unroll
            for (int t = 0; t < 13; ++t) {
                u32 Bh[2], Bl[2];
                ldx2(Bh, sb + SM_W1H + t * 1152 + bB + ks * 32);
                ldx2(Bl, sb + SM_W1L + t * 1152 + bB + ks * 32);
                mma16816(acc[t], Ah, Bh);
                mma16816(acc[t], Ah, Bl);
                mma16816(acc[t], Al, Bh);
            }
        }
    }

    // ---- epi2: direct float2 STG from accumulators ----
    {
        const int cb = 2 * (lane & 3);
        const size_t rb = (size_t)(n0 + 16 * w + (lane >> 2)) * 10000 + (size_t)m * 100;
#pragma unroll
        for (int t = 0; t < 13; ++t) {
            int c = 8 * t + cb;
            if (c < 100) {
                *(float2*)(out + rb + c)         = make_float2(acc[t][0], acc[t][1]);
                *(float2*)(out + rb + 80000 + c) = make_float2(acc[t][2], acc[t][3]);
            }
        }
    }
}

// ---------------------------------- launch -----------------------------------
extern "C" void kernel_launch(void* const* d_in, const int* in_sizes, int n_in,
                              void* d_out, int out_size) {
    const float* x;
    const float* ms_vs;
    if (in_sizes[0] == 2306) { ms_vs = (const float*)d_in[0]; x = (const float*)d_in[1]; }
    else                     { x = (const float*)d_in[0];     ms_vs = (const float*)d_in[1]; }
    float* out = (float*)d_out;

    u32 k0a, k0b, k1a, k1b;
    threefry(0u, 42u, 0u, 0u, k0a, k0b);
    threefry(0u, 42u, 0u, 1u, k1a, k1b);

    setup1_kernel<<<(E0 + E1 + TAILN + 255) / 256, 256>>>(ms_vs, out + OUT_PRED,
                                                          k0a, k0b, k1a, k1b);
    setup2_kernel<<<(S2TOT + 255) / 256, 256>>>(x);

    cudaFuncSetAttribute(pred_kernel, cudaFuncAttributeMaxDynamicSharedMemorySize, SM_BYTES);
    pred_kernel<<<dim3(NROWS / 128, NSAMP), 256, SM_BYTES>>>(out);
}

// round 14
// speedup vs baseline: 1.1514x; 1.1514x over previous
#include <cuda_runtime.h>
#include <cstdint>

// Problem constants
#define LEN_M   1088
#define MPRI    65
#define NSAMP   100
#define NROWS   16384
#define DD1     17
#define DH      64
#define OUT_PRED ((size_t)NROWS * NSAMP * NSAMP)

typedef unsigned long long u64;
typedef uint32_t u32;

// ---------------- device globals (scratch; no allocation allowed) ------------
__device__ float g_W0T[NSAMP * LEN_M];            // [m][j], j=k*64+h  (fp32)
__device__ float g_w1[MPRI * NSAMP];              // [d][c]            (fp32)
// bf16 hi/lo operand images (ldmatrix rows, padded strides, 16B aligned):
__device__ __align__(16) u32 g_ximgH[NROWS * 12];   // [n][16k], 48B stride
__device__ __align__(16) u32 g_ximgL[NROWS * 12];
__device__ __align__(16) u32 g_w0imgH[NSAMP * 64 * 12];  // [m][h][16k], 48B
__device__ __align__(16) u32 g_w0imgL[NSAMP * 64 * 12];
__device__ __align__(16) u32 g_w1imgH[104 * 36];    // [c][64k pad 72], 144B
__device__ __align__(16) u32 g_w1imgL[104 * 36];
__device__ __align__(16) float g_x16[NROWS];        // x[:,16] packed fp32
__device__ __align__(16) float g_w0k16[NSAMP * 64]; // W0[16][h] per m, fp32

// ---------------- Threefry2x32 (exact JAX rotation/key schedule) -------------
__host__ __device__ inline void threefry(u32 k0, u32 k1, u32 c0, u32 c1,
                                         u32& o0, u32& o1) {
    u32 ks2 = k0 ^ k1 ^ 0x1BD11BDAu;
    u32 x0 = c0 + k0, x1 = c1 + k1;
#define TF_ROUND(r) { x0 += x1; x1 = (x1 << (r)) | (x1 >> (32 - (r))); x1 ^= x0; }
    TF_ROUND(13) TF_ROUND(15) TF_ROUND(26) TF_ROUND(6)
    x0 += k1;  x1 += ks2 + 1u;
    TF_ROUND(17) TF_ROUND(29) TF_ROUND(16) TF_ROUND(24)
    x0 += ks2; x1 += k0 + 2u;
    TF_ROUND(13) TF_ROUND(15) TF_ROUND(26) TF_ROUND(6)
    x0 += k0;  x1 += k1 + 3u;
    TF_ROUND(17) TF_ROUND(29) TF_ROUND(16) TF_ROUND(24)
    x0 += k1;  x1 += ks2 + 4u;
    TF_ROUND(13) TF_ROUND(15) TF_ROUND(26) TF_ROUND(6)
    x0 += ks2; x1 += k0 + 5u;
#undef TF_ROUND
    o0 = x0; o1 = x1;
}

__device__ inline float erfinv_xla(float x) {
    float w = -log1pf(-x * x);
    float p;
    if (w < 5.0f) {
        w -= 2.5f;
        p = 2.81022636e-08f;
        p = fmaf(p, w, 3.43273939e-07f);
        p = fmaf(p, w, -3.5233877e-06f);
        p = fmaf(p, w, -4.39150654e-06f);
        p = fmaf(p, w, 0.00021858087f);
        p = fmaf(p, w, -0.00125372503f);
        p = fmaf(p, w, -0.00417768164f);
        p = fmaf(p, w, 0.246640727f);
        p = fmaf(p, w, 1.50140941f);
    } else {
        w = sqrtf(w) - 3.0f;
        p = -0.000200214257f;
        p = fmaf(p, w, 0.000100950558f);
        p = fmaf(p, w, 0.00134934322f);
        p = fmaf(p, w, -0.00367342844f);
        p = fmaf(p, w, 0.00573950773f);
        p = fmaf(p, w, -0.0076224613f);
        p = fmaf(p, w, 0.00943887047f);
        p = fmaf(p, w, 1.00167406f);
        p = fmaf(p, w, 2.83297682f);
    }
    return p * x;
}

__device__ inline float bits_to_normal(u32 bits) {
    float f = __uint_as_float((bits >> 9) | 0x3f800000u) - 1.0f;
    const float lo = -0.99999994f;
    float u = __fadd_rn(__fmul_rn(f, 2.0f), lo);
    u = fmaxf(lo, u);
    return 1.4142135381698608f * erfinv_xla(u);
}

// ---------------- setup1: sample weights (fp32) + output tail ----------------
#define E0 108800
#define E1 6500
#define TAILN 2306

__global__ void setup1_kernel(const float* __restrict__ ms_vs,
                              float* __restrict__ out_tail,
                              u32 k0a, u32 k0b, u32 k1a, u32 k1b) {
    int t = blockIdx.x * blockDim.x + threadIdx.x;
    if (t < E0) {
        u32 o0, o1;
        threefry(k0a, k0b, 0u, (u32)t, o0, o1);
        float n = bits_to_normal(o0 ^ o1);
        int j = t / 100, m = t - j * 100;
        float v = fabsf(ms_vs[1153 + j]) + 1e-6f;
        g_W0T[m * LEN_M + j] = fmaf(n, sqrtf(v), ms_vs[j]);
    } else if (t < E0 + E1) {
        int i = t - E0;
        u32 o0, o1;
        threefry(k1a, k1b, 0u, (u32)i, o0, o1);
        float n = bits_to_normal(o0 ^ o1);
        int d = i / 100, c = i - d * 100;
        float v = fabsf(ms_vs[2241 + d]) + 1e-6f;
        g_w1[d * 100 + c] = fmaf(n, sqrtf(v), ms_vs[1088 + d]);
    } else if (t < E0 + E1 + TAILN) {
        int q = t - E0 - E1;
        float val;
        if (q < 1088)       val = ms_vs[q];
        else if (q < 2176)  val = fabsf(ms_vs[1153 + (q - 1088)]) + 1e-6f;
        else if (q < 2241)  val = ms_vs[1088 + (q - 2176)];
        else                val = fabsf(ms_vs[q]) + 1e-6f;
        out_tail[q] = val;
    }
}

// ---------------- setup2: build bf16 hi/lo operand images --------------------
__device__ inline void bf16split2(float a, float b, u32& H, u32& L) {
    asm("cvt.rn.bf16x2.f32 %0, %1, %2;" : "=r"(H) : "f"(b), "f"(a));  // lo half = a
    float hf0 = __uint_as_float(H << 16);
    float hf1 = __uint_as_float(H & 0xFFFF0000u);
    float l0 = a - hf0, l1 = b - hf1;
    asm("cvt.rn.bf16x2.f32 %0, %1, %2;" : "=r"(L) : "f"(l1), "f"(l0));
}

#define SX  131072   // X slots: 16384*8
#define SX1 16384    // x16
#define SW0 51200    // 100*64*8
#define SWK 6400     // w0k16
#define SW1 3744     // 104*36
#define S2TOT (SX + SX1 + SW0 + SWK + SW1)

__global__ void setup2_kernel(const float* __restrict__ x) {
    int s = blockIdx.x * blockDim.x + threadIdx.x;
    if (s < SX) {
        int n = s >> 3, p = s & 7;
        int k = 2 * p;
        float a = x[n * DD1 + k];
        float b = x[n * DD1 + k + 1];
        u32 H, L; bf16split2(a, b, H, L);
        g_ximgH[n * 12 + p] = H;
        g_ximgL[n * 12 + p] = L;
    } else if (s < SX + SX1) {
        int n = s - SX;
        g_x16[n] = x[n * DD1 + 16];
    } else if (s < SX + SX1 + SW0) {
        int r = s - SX - SX1;
        int m = r >> 9, t = r & 511;
        int h = t >> 3, p = t & 7;
        int k = 2 * p;
        float a = g_W0T[m * LEN_M + k * DH + h];
        float b = g_W0T[m * LEN_M + (k + 1) * DH + h];
        u32 H, L; bf16split2(a, b, H, L);
        g_w0imgH[(m * 64 + h) * 12 + p] = H;
        g_w0imgL[(m * 64 + h) * 12 + p] = L;
    } else if (s < SX + SX1 + SW0 + SWK) {
        int r = s - SX - SX1 - SW0;
        int m = r >> 6, h = r & 63;
        g_w0k16[r] = g_W0T[m * LEN_M + 16 * DH + h];
    } else if (s < S2TOT) {
        int r = s - SX - SX1 - SW0 - SWK;
        int c = r / 36, p = r - c * 36;
        int k = 2 * p;                            // K idx -> w1 row d=k+1
        float a = (k     < 64 && c < 100) ? g_w1[(k + 1) * 100 + c] : 0.0f;
        float b = (k + 1 < 64 && c < 100) ? g_w1[(k + 2) * 100 + c] : 0.0f;
        u32 H, L; bf16split2(a, b, H, L);
        g_w1imgH[r] = H;
        g_w1imgL[r] = L;
    }
}

// ---------------- mma.sync / ldmatrix / mbarrier helpers ---------------------
__device__ __forceinline__ void ldx4(u32* r, u32 addr) {
    asm volatile("ldmatrix.sync.aligned.m8n8.x4.shared.b16 {%0,%1,%2,%3}, [%4];"
                 : "=r"(r[0]), "=r"(r[1]), "=r"(r[2]), "=r"(r[3]) : "r"(addr));
}
__device__ __forceinline__ void ldx2(u32* r, u32 addr) {
    asm volatile("ldmatrix.sync.aligned.m8n8.x2.shared.b16 {%0,%1}, [%2];"
                 : "=r"(r[0]), "=r"(r[1]) : "r"(addr));
}
__device__ __forceinline__ void mma16816(float* d, const u32* a, const u32* b) {
    asm volatile("mma.sync.aligned.m16n8k16.row.col.f32.bf16.bf16.f32 "
                 "{%0,%1,%2,%3}, {%4,%5,%6,%7}, {%8,%9}, {%0,%1,%2,%3};"
                 : "+f"(d[0]), "+f"(d[1]), "+f"(d[2]), "+f"(d[3])
                 : "r"(a[0]), "r"(a[1]), "r"(a[2]), "r"(a[3]), "r"(b[0]), "r"(b[1]));
}
#define MBAR_INIT(a, n)   asm volatile("mbarrier.init.shared.b64 [%0], %1;" :: "r"(a), "r"((u32)(n)) : "memory")
#define MBAR_EXPECT(a, b) asm volatile("mbarrier.arrive.expect_tx.shared.b64 _, [%0], %1;" :: "r"(a), "r"((u32)(b)) : "memory")
__device__ __forceinline__ void mbar_wait(u32 addr, u32 parity) {
    asm volatile("{\n\t.reg .pred P1;\n\t"
        "WAIT_LOOP_%=:\n\t"
        "mbarrier.try_wait.parity.acquire.cta.shared::cta.b64 P1, [%0], %1, 0x989680;\n\t"
        "@P1 bra.uni WAIT_DONE_%=;\n\t"
        "bra.uni WAIT_LOOP_%=;\n\t"
        "WAIT_DONE_%=:\n\t}"
        :: "r"(addr), "r"(parity) : "memory");
}
__device__ __forceinline__ void bulk_cp(u32 dst_smem, const void* src, u32 bytes, u32 mbar) {
    asm volatile("cp.async.bulk.shared::cluster.global.mbarrier::complete_tx::bytes "
                 "[%0], [%1], %2, [%3];"
                 :: "r"(dst_smem), "l"(src), "r"(bytes), "r"(mbar) : "memory");
}

// ---------------- pred kernel ------------------------------------------------
// smem overlay layout (bytes):
//   [0..1024)       mbarrier/header
//   [1024..19456)   fill: XH(6144) XL(6144) W0H(3072) W0L(3072)
//                   later: ZH(18432) overlays this whole region
//   [19456..20640)  X16(512) W0K(256) BS(416)   (live through epi1/acc-init)
//   [20736..50688)  W1H(14976) W1L(14976)       (live through GEMM2)
//   [50688..69120)  ZL(18432)
#define SM_XH   1024
#define SM_XL   7168
#define SM_W0H  13312
#define SM_W0L  16384
#define SM_X16  19456
#define SM_W0K  19968
#define SM_BS   20224
#define SM_W1H  20736
#define SM_W1L  35712
#define SM_ZH   1024      // overlays X/W0 after GEMM1
#define SM_ZL   50688
#define SM_BYTES 69120
#define FILL_BYTES 49552u

__global__ void __launch_bounds__(256, 3) pred_kernel(float* __restrict__ out) {
    extern __shared__ char sm[];
    u32 sb;
    asm("{ .reg .u64 t; cvta.to.shared.u64 t, %1; cvt.u32.u64 %0, t; }"
        : "=r"(sb) : "l"(sm));

    const int tid  = threadIdx.x;
    const int lane = tid & 31;
    const int w    = tid >> 5;              // 0..7: n-strip rows 16w..16w+15
    const int m    = blockIdx.y;
    const int n0   = blockIdx.x * 128;

    if (tid == 0) {
        MBAR_INIT(sb + 8, 1);
        MBAR_EXPECT(sb + 8, FILL_BYTES);
        bulk_cp(sb + SM_XH,  g_ximgH  + (size_t)n0 * 12, 6144u, sb + 8);
        bulk_cp(sb + SM_XL,  g_ximgL  + (size_t)n0 * 12, 6144u, sb + 8);
        bulk_cp(sb + SM_W0H, g_w0imgH + (size_t)m * 768, 3072u, sb + 8);
        bulk_cp(sb + SM_W0L, g_w0imgL + (size_t)m * 768, 3072u, sb + 8);
        bulk_cp(sb + SM_W1H, g_w1imgH, 14976u, sb + 8);
        bulk_cp(sb + SM_W1L, g_w1imgL, 14976u, sb + 8);
        bulk_cp(sb + SM_X16, g_x16 + n0, 512u, sb + 8);
        bulk_cp(sb + SM_W0K, g_w0k16 + m * 64, 256u, sb + 8);
        bulk_cp(sb + SM_BS,  g_w1, 400u, sb + 8);
    }
    __syncthreads();
    mbar_wait(sb + 8, 0);

    // ---- GEMM1: D1[16 rows x 64 h] per warp; K=16, 3-product split ----
    float acc1[8][4];
#pragma unroll
    for (int t = 0; t < 8; ++t)
#pragma unroll
        for (int j = 0; j < 4; ++j) acc1[t][j] = 0.0f;

    {
        u32 Ah[4], Al[4];
        ldx4(Ah, sb + SM_XH + (16 * w + (lane & 15)) * 48 + (lane >> 4) * 16);
        ldx4(Al, sb + SM_XL + (16 * w + (lane & 15)) * 48 + (lane >> 4) * 16);
        const u32 bB = (lane & 7) * 48 + ((lane >> 3) & 1) * 16;
#pragma unroll
        for (int t = 0; t < 8; ++t) {
            u32 Bh[2], Bl[2];
            ldx2(Bh, sb + SM_W0H + t * 384 + bB);
            ldx2(Bl, sb + SM_W0L + t * 384 + bB);
            mma16816(acc1[t], Ah, Bh);
            mma16816(acc1[t], Ah, Bl);
            mma16816(acc1[t], Al, Bh);
        }
    }
    __syncthreads();   // all warps done reading X/W0 before ZH overlays them

    // ---- epi1: + exact fp32 k=16 term, relu, bf16 split -> Zh/Zl smem ----
    {
        const int r0 = 16 * w + (lane >> 2);
        const int cb = 2 * (lane & 3);
        const float* x16s = (const float*)(sm + SM_X16);
        const float* w0ks = (const float*)(sm + SM_W0K);
        const float xa = x16s[r0], xb = x16s[r0 + 8];
#pragma unroll
        for (int t = 0; t < 8; ++t) {
            const float wa = w0ks[8 * t + cb], wb = w0ks[8 * t + cb + 1];
            u32 H, L;
            float z0 = fmaxf(fmaf(xa, wa, acc1[t][0]), 0.0f);
            float z1 = fmaxf(fmaf(xa, wb, acc1[t][1]), 0.0f);
            bf16split2(z0, z1, H, L);
            u32 off = r0 * 144 + (8 * t + cb) * 2;
            *(u32*)(sm + SM_ZH + off) = H;
            *(u32*)(sm + SM_ZL + off) = L;
            float z2 = fmaxf(fmaf(xb, wa, acc1[t][2]), 0.0f);
            float z3 = fmaxf(fmaf(xb, wb, acc1[t][3]), 0.0f);
            bf16split2(z2, z3, H, L);
            off += 8 * 144;
            *(u32*)(sm + SM_ZH + off) = H;
            *(u32*)(sm + SM_ZL + off) = L;
        }
    }
    __syncthreads();

    // ---- GEMM2: D2[16 rows x 104 c] per warp; K=64; bias preloaded ----
    float acc[13][4];
    {
        const int cb = 2 * (lane & 3);
        const float* bs = (const float*)(sm + SM_BS);
#pragma unroll
        for (int t = 0; t < 13; ++t) {
            float b0 = bs[8 * t + cb], b1 = bs[8 * t + cb + 1];
            acc[t][0] = b0; acc[t][1] = b1; acc[t][2] = b0; acc[t][3] = b1;
        }
    }
    {
        const u32 aH = sb + SM_ZH + (16 * w + (lane & 15)) * 144 + (lane >> 4) * 16;
        const u32 aL = sb + SM_ZL + (16 * w + (lane & 15)) * 144 + (lane >> 4) * 16;
        const u32 bB = (lane & 7) * 144 + ((lane >> 3) & 1) * 16;
#pragma unroll
        for (int ks = 0; ks < 4; ++ks) {
            u32 Ah[4], Al[4];
            ldx4(Ah, aH + ks * 32);
            ldx4(Al, aL + ks * 32);
#pragma unroll
            for (int t = 0; t < 13; ++t) {
                u32 Bh[2], Bl[2];
                ldx2(Bh, sb + SM_W1H + t * 1152 + bB + ks * 32);
                ldx2(Bl, sb + SM_W1L + t * 1152 + bB + ks * 32);
                mma16816(acc[t], Ah, Bh);
                mma16816(acc[t], Ah, Bl);
                mma16816(acc[t], Al, Bh);
            }
        }
    }

    // ---- epi2: direct float2 STG from accumulators ----
    {
        const int cb = 2 * (lane & 3);
        const size_t rb = (size_t)(n0 + 16 * w + (lane >> 2)) * 10000 + (size_t)m * 100;
#pragma unroll
        for (int t = 0; t < 13; ++t) {
            int c = 8 * t + cb;
            if (c < 100) {
                *(float2*)(out + rb + c)         = make_float2(acc[t][0], acc[t][1]);
                *(float2*)(out + rb + 80000 + c) = make_float2(acc[t][2], acc[t][3]);
            }
        }
    }
}

// ---------------------------------- launch -----------------------------------
extern "C" void kernel_launch(void* const* d_in, const int* in_sizes, int n_in,
                              void* d_out, int out_size) {
    const float* x;
    const float* ms_vs;
    if (in_sizes[0] == 2306) { ms_vs = (const float*)d_in[0]; x = (const float*)d_in[1]; }
    else                     { x = (const float*)d_in[0];     ms_vs = (const float*)d_in[1]; }
    float* out = (float*)d_out;

    u32 k0a, k0b, k1a, k1b;
    threefry(0u, 42u, 0u, 0u, k0a, k0b);
    threefry(0u, 42u, 0u, 1u, k1a, k1b);

    setup1_kernel<<<(E0 + E1 + TAILN + 255) / 256, 256>>>(ms_vs, out + OUT_PRED,
                                                          k0a, k0b, k1a, k1b);
    setup2_kernel<<<(S2TOT + 255) / 256, 256>>>(x);

    cudaFuncSetAttribute(pred_kernel, cudaFuncAttributeMaxDynamicSharedMemorySize, SM_BYTES);
    pred_kernel<<<dim3(NROWS / 128, NSAMP), 256, SM_BYTES>>>(out);
}

// round 15
// speedup vs baseline: 1.2988x; 1.1280x over previous
#include <cuda_runtime.h>
#include <cuda_fp16.h>
#include <cstdint>

// Problem constants
#define LEN_M   1088
#define MPRI    65
#define NSAMP   100
#define NROWS   16384
#define DD1     17
#define DH      64
#define OUT_PRED ((size_t)NROWS * NSAMP * NSAMP)

typedef unsigned long long u64;
typedef uint32_t u32;

// ---------------- device globals (scratch; no allocation allowed) ------------
__device__ float g_W0T[NSAMP * LEN_M];            // [m][j], j=k*64+h  (fp32)
__device__ float g_w1[MPRI * NSAMP];              // [d][c]            (fp32)
// fp16 hi/lo operand images (ldmatrix rows, padded strides, 16B aligned):
__device__ __align__(16) u32 g_ximgH[NROWS * 12];   // [n][16k], 48B stride
__device__ __align__(16) u32 g_ximgL[NROWS * 12];
__device__ __align__(16) u32 g_w0imgH[NSAMP * 64 * 12];  // [m][h][16k], 48B
__device__ __align__(16) u32 g_w0imgL[NSAMP * 64 * 12];
__device__ __align__(16) u32 g_w1imgH[104 * 36];    // [c][64k pad 72], 144B
__device__ __align__(16) u32 g_w1imgL[104 * 36];
__device__ __align__(16) float g_x16[NROWS];        // x[:,16] packed fp32
__device__ __align__(16) float g_w0k16[NSAMP * 64]; // W0[16][h] per m, fp32

// ---------------- Threefry2x32 (exact JAX rotation/key schedule) -------------
__host__ __device__ inline void threefry(u32 k0, u32 k1, u32 c0, u32 c1,
                                         u32& o0, u32& o1) {
    u32 ks2 = k0 ^ k1 ^ 0x1BD11BDAu;
    u32 x0 = c0 + k0, x1 = c1 + k1;
#define TF_ROUND(r) { x0 += x1; x1 = (x1 << (r)) | (x1 >> (32 - (r))); x1 ^= x0; }
    TF_ROUND(13) TF_ROUND(15) TF_ROUND(26) TF_ROUND(6)
    x0 += k1;  x1 += ks2 + 1u;
    TF_ROUND(17) TF_ROUND(29) TF_ROUND(16) TF_ROUND(24)
    x0 += ks2; x1 += k0 + 2u;
    TF_ROUND(13) TF_ROUND(15) TF_ROUND(26) TF_ROUND(6)
    x0 += k0;  x1 += k1 + 3u;
    TF_ROUND(17) TF_ROUND(29) TF_ROUND(16) TF_ROUND(24)
    x0 += k1;  x1 += ks2 + 4u;
    TF_ROUND(13) TF_ROUND(15) TF_ROUND(26) TF_ROUND(6)
    x0 += ks2; x1 += k0 + 5u;
#undef TF_ROUND
    o0 = x0; o1 = x1;
}

__device__ inline float erfinv_xla(float x) {
    float w = -log1pf(-x * x);
    float p;
    if (w < 5.0f) {
        w -= 2.5f;
        p = 2.81022636e-08f;
        p = fmaf(p, w, 3.43273939e-07f);
        p = fmaf(p, w, -3.5233877e-06f);
        p = fmaf(p, w, -4.39150654e-06f);
        p = fmaf(p, w, 0.00021858087f);
        p = fmaf(p, w, -0.00125372503f);
        p = fmaf(p, w, -0.00417768164f);
        p = fmaf(p, w, 0.246640727f);
        p = fmaf(p, w, 1.50140941f);
    } else {
        w = sqrtf(w) - 3.0f;
        p = -0.000200214257f;
        p = fmaf(p, w, 0.000100950558f);
        p = fmaf(p, w, 0.00134934322f);
        p = fmaf(p, w, -0.00367342844f);
        p = fmaf(p, w, 0.00573950773f);
        p = fmaf(p, w, -0.0076224613f);
        p = fmaf(p, w, 0.00943887047f);
        p = fmaf(p, w, 1.00167406f);
        p = fmaf(p, w, 2.83297682f);
    }
    return p * x;
}

__device__ inline float bits_to_normal(u32 bits) {
    float f = __uint_as_float((bits >> 9) | 0x3f800000u) - 1.0f;
    const float lo = -0.99999994f;
    float u = __fadd_rn(__fmul_rn(f, 2.0f), lo);
    u = fmaxf(lo, u);
    return 1.4142135381698608f * erfinv_xla(u);
}

// ---------------- setup1: sample weights (fp32) + output tail ----------------
#define E0 108800
#define E1 6500
#define TAILN 2306

__global__ void setup1_kernel(const float* __restrict__ ms_vs,
                              float* __restrict__ out_tail,
                              u32 k0a, u32 k0b, u32 k1a, u32 k1b) {
    int t = blockIdx.x * blockDim.x + threadIdx.x;
    if (t < E0) {
        u32 o0, o1;
        threefry(k0a, k0b, 0u, (u32)t, o0, o1);
        float n = bits_to_normal(o0 ^ o1);
        int j = t / 100, m = t - j * 100;
        float v = fabsf(ms_vs[1153 + j]) + 1e-6f;
        g_W0T[m * LEN_M + j] = fmaf(n, sqrtf(v), ms_vs[j]);
    } else if (t < E0 + E1) {
        int i = t - E0;
        u32 o0, o1;
        threefry(k1a, k1b, 0u, (u32)i, o0, o1);
        float n = bits_to_normal(o0 ^ o1);
        int d = i / 100, c = i - d * 100;
        float v = fabsf(ms_vs[2241 + d]) + 1e-6f;
        g_w1[d * 100 + c] = fmaf(n, sqrtf(v), ms_vs[1088 + d]);
    } else if (t < E0 + E1 + TAILN) {
        int q = t - E0 - E1;
        float val;
        if (q < 1088)       val = ms_vs[q];
        else if (q < 2176)  val = fabsf(ms_vs[1153 + (q - 1088)]) + 1e-6f;
        else if (q < 2241)  val = ms_vs[1088 + (q - 2176)];
        else                val = fabsf(ms_vs[q]) + 1e-6f;
        out_tail[q] = val;
    }
}

// ---------------- setup2: build fp16 hi/lo operand images --------------------
__device__ inline void f16split2(float a, float b, u32& H, u32& L) {
    half2 h = __floats2half2_rn(a, b);          // .x = a (low 16 bits)
    H = *(u32*)&h;
    float la = a - __half2float(__low2half(h));
    float lb = b - __half2float(__high2half(h));
    half2 l = __floats2half2_rn(la, lb);
    L = *(u32*)&l;
}

#define SX  131072   // X slots: 16384*8
#define SX1 16384    // x16
#define SW0 51200    // 100*64*8
#define SWK 6400     // w0k16
#define SW1 3744     // 104*36
#define S2TOT (SX + SX1 + SW0 + SWK + SW1)

__global__ void setup2_kernel(const float* __restrict__ x) {
    int s = blockIdx.x * blockDim.x + threadIdx.x;
    if (s < SX) {
        int n = s >> 3, p = s & 7;
        int k = 2 * p;
        float a = x[n * DD1 + k];
        float b = x[n * DD1 + k + 1];
        u32 H, L; f16split2(a, b, H, L);
        g_ximgH[n * 12 + p] = H;
        g_ximgL[n * 12 + p] = L;
    } else if (s < SX + SX1) {
        int n = s - SX;
        g_x16[n] = x[n * DD1 + 16];
    } else if (s < SX + SX1 + SW0) {
        int r = s - SX - SX1;
        int m = r >> 9, t = r & 511;
        int h = t >> 3, p = t & 7;
        int k = 2 * p;
        float a = g_W0T[m * LEN_M + k * DH + h];
        float b = g_W0T[m * LEN_M + (k + 1) * DH + h];
        u32 H, L; f16split2(a, b, H, L);
        g_w0imgH[(m * 64 + h) * 12 + p] = H;
        g_w0imgL[(m * 64 + h) * 12 + p] = L;
    } else if (s < SX + SX1 + SW0 + SWK) {
        int r = s - SX - SX1 - SW0;
        int m = r >> 6, h = r & 63;
        g_w0k16[r] = g_W0T[m * LEN_M + 16 * DH + h];
    } else if (s < S2TOT) {
        int r = s - SX - SX1 - SW0 - SWK;
        int c = r / 36, p = r - c * 36;
        int k = 2 * p;                            // K idx -> w1 row d=k+1
        float a = (k     < 64 && c < 100) ? g_w1[(k + 1) * 100 + c] : 0.0f;
        float b = (k + 1 < 64 && c < 100) ? g_w1[(k + 2) * 100 + c] : 0.0f;
        u32 H, L; f16split2(a, b, H, L);
        g_w1imgH[r] = H;
        g_w1imgL[r] = L;
    }
}

// ---------------- mma.sync / ldmatrix / mbarrier helpers ---------------------
__device__ __forceinline__ void ldx4(u32* r, u32 addr) {
    asm volatile("ldmatrix.sync.aligned.m8n8.x4.shared.b16 {%0,%1,%2,%3}, [%4];"
                 : "=r"(r[0]), "=r"(r[1]), "=r"(r[2]), "=r"(r[3]) : "r"(addr));
}
__device__ __forceinline__ void ldx2(u32* r, u32 addr) {
    asm volatile("ldmatrix.sync.aligned.m8n8.x2.shared.b16 {%0,%1}, [%2];"
                 : "=r"(r[0]), "=r"(r[1]) : "r"(addr));
}
__device__ __forceinline__ void mma16816(float* d, const u32* a, const u32* b) {
    asm volatile("mma.sync.aligned.m16n8k16.row.col.f32.f16.f16.f32 "
                 "{%0,%1,%2,%3}, {%4,%5,%6,%7}, {%8,%9}, {%0,%1,%2,%3};"
                 : "+f"(d[0]), "+f"(d[1]), "+f"(d[2]), "+f"(d[3])
                 : "r"(a[0]), "r"(a[1]), "r"(a[2]), "r"(a[3]), "r"(b[0]), "r"(b[1]));
}
#define MBAR_INIT(a, n)   asm volatile("mbarrier.init.shared.b64 [%0], %1;" :: "r"(a), "r"((u32)(n)) : "memory")
#define MBAR_EXPECT(a, b) asm volatile("mbarrier.arrive.expect_tx.shared.b64 _, [%0], %1;" :: "r"(a), "r"((u32)(b)) : "memory")
__device__ __forceinline__ void mbar_wait(u32 addr, u32 parity) {
    asm volatile("{\n\t.reg .pred P1;\n\t"
        "WAIT_LOOP_%=:\n\t"
        "mbarrier.try_wait.parity.acquire.cta.shared::cta.b64 P1, [%0], %1, 0x989680;\n\t"
        "@P1 bra.uni WAIT_DONE_%=;\n\t"
        "bra.uni WAIT_LOOP_%=;\n\t"
        "WAIT_DONE_%=:\n\t}"
        :: "r"(addr), "r"(parity) : "memory");
}
__device__ __forceinline__ void bulk_cp(u32 dst_smem, const void* src, u32 bytes, u32 mbar) {
    asm volatile("cp.async.bulk.shared::cluster.global.mbarrier::complete_tx::bytes "
                 "[%0], [%1], %2, [%3];"
                 :: "r"(dst_smem), "l"(src), "r"(bytes), "r"(mbar) : "memory");
}

// ---------------- pred kernel ------------------------------------------------
// smem overlay layout (bytes):
//   [0..1024)       mbarrier/header
//   [1024..19456)   fill: XH(6144) XL(6144) W0H(3072) W0L(3072)
//                   later: ZH(18432) overlays this whole region exactly
//   [19456..20640)  X16(512) W0K(256) BS(416)
//   [20736..50688)  W1H(14976) W1L(14976)
#define SM_XH   1024
#define SM_XL   7168
#define SM_W0H  13312
#define SM_W0L  16384
#define SM_X16  19456
#define SM_W0K  19968
#define SM_BS   20224
#define SM_W1H  20736
#define SM_W1L  35712
#define SM_ZH   1024      // overlays X/W0 after GEMM1
#define SM_BYTES 50688
#define FILL_BYTES 49552u

__global__ void __launch_bounds__(256, 4) pred_kernel(float* __restrict__ out) {
    extern __shared__ char sm[];
    u32 sb;
    asm("{ .reg .u64 t; cvta.to.shared.u64 t, %1; cvt.u32.u64 %0, t; }"
        : "=r"(sb) : "l"(sm));

    const int tid  = threadIdx.x;
    const int lane = tid & 31;
    const int w    = tid >> 5;              // 0..7: n-strip rows 16w..16w+15
    const int m    = blockIdx.y;
    const int n0   = blockIdx.x * 128;

    if (tid == 0) {
        MBAR_INIT(sb + 8, 1);
        MBAR_EXPECT(sb + 8, FILL_BYTES);
        bulk_cp(sb + SM_XH,  g_ximgH  + (size_t)n0 * 12, 6144u, sb + 8);
        bulk_cp(sb + SM_XL,  g_ximgL  + (size_t)n0 * 12, 6144u, sb + 8);
        bulk_cp(sb + SM_W0H, g_w0imgH + (size_t)m * 768, 3072u, sb + 8);
        bulk_cp(sb + SM_W0L, g_w0imgL + (size_t)m * 768, 3072u, sb + 8);
        bulk_cp(sb + SM_W1H, g_w1imgH, 14976u, sb + 8);
        bulk_cp(sb + SM_W1L, g_w1imgL, 14976u, sb + 8);
        bulk_cp(sb + SM_X16, g_x16 + n0, 512u, sb + 8);
        bulk_cp(sb + SM_W0K, g_w0k16 + m * 64, 256u, sb + 8);
        bulk_cp(sb + SM_BS,  g_w1, 400u, sb + 8);
    }
    __syncthreads();
    mbar_wait(sb + 8, 0);

    // ---- GEMM1: D1[16 rows x 64 h] per warp; K=16, 3-product fp16 split ----
    float acc1[8][4];
#pragma unroll
    for (int t = 0; t < 8; ++t)
#pragma unroll
        for (int j = 0; j < 4; ++j) acc1[t][j] = 0.0f;

    {
        u32 Ah[4], Al[4];
        ldx4(Ah, sb + SM_XH + (16 * w + (lane & 15)) * 48 + (lane >> 4) * 16);
        ldx4(Al, sb + SM_XL + (16 * w + (lane & 15)) * 48 + (lane >> 4) * 16);
        // paired B load: rows = 16*tp + 8*(lane>>4) + (lane&7), col = ((lane>>3)&1)*16
        const u32 bB = (16 * 0) /*per tp below*/;
        const u32 rowsel = (u32)(8 * (lane >> 4) + (lane & 7)) * 48 + (u32)((lane >> 3) & 1) * 16;
        (void)bB;
#pragma unroll
        for (int tp = 0; tp < 4; ++tp) {
            u32 B[4];
            ldx4(B, sb + SM_W0H + tp * 16 * 48 + rowsel);
            mma16816(acc1[2 * tp],     Ah, B);
            mma16816(acc1[2 * tp + 1], Ah, B + 2);
            u32 Bl[4];
            ldx4(Bl, sb + SM_W0L + tp * 16 * 48 + rowsel);
            mma16816(acc1[2 * tp],     Al, B);
            mma16816(acc1[2 * tp + 1], Al, B + 2);
            mma16816(acc1[2 * tp],     Ah, Bl);
            mma16816(acc1[2 * tp + 1], Ah, Bl + 2);
        }
    }
    __syncthreads();   // all warps done reading X/W0 before ZH overlays them

    // ---- epi1: + exact fp32 k=16 term, relu, fp16 round -> ZH smem ----
    {
        const int r0 = 16 * w + (lane >> 2);
        const int cb = 2 * (lane & 3);
        const float* x16s = (const float*)(sm + SM_X16);
        const float* w0ks = (const float*)(sm + SM_W0K);
        const float xa = x16s[r0], xb = x16s[r0 + 8];
#pragma unroll
        for (int t = 0; t < 8; ++t) {
            const float wa = w0ks[8 * t + cb], wb = w0ks[8 * t + cb + 1];
            float z0 = fmaxf(fmaf(xa, wa, acc1[t][0]), 0.0f);
            float z1 = fmaxf(fmaf(xa, wb, acc1[t][1]), 0.0f);
            half2 h01 = __floats2half2_rn(z0, z1);
            u32 off = r0 * 144 + (8 * t + cb) * 2;
            *(u32*)(sm + SM_ZH + off) = *(u32*)&h01;
            float z2 = fmaxf(fmaf(xb, wa, acc1[t][2]), 0.0f);
            float z3 = fmaxf(fmaf(xb, wb, acc1[t][3]), 0.0f);
            half2 h23 = __floats2half2_rn(z2, z3);
            off += 8 * 144;
            *(u32*)(sm + SM_ZH + off) = *(u32*)&h23;
        }
    }
    __syncthreads();

    // ---- GEMM2: D2[16 rows x 104 c] per warp; K=64; 2-product (W1 split) ----
    float acc[13][4];
    {
        const int cb = 2 * (lane & 3);
        const float* bs = (const float*)(sm + SM_BS);
#pragma unroll
        for (int t = 0; t < 13; ++t) {
            float b0 = bs[8 * t + cb], b1 = bs[8 * t + cb + 1];
            acc[t][0] = b0; acc[t][1] = b1; acc[t][2] = b0; acc[t][3] = b1;
        }
    }
    {
        const u32 aA = sb + SM_ZH + (16 * w + (lane & 15)) * 144 + (lane >> 4) * 16;
        const u32 rowsel = (u32)(8 * (lane >> 4) + (lane & 7)) * 144 + (u32)((lane >> 3) & 1) * 16;
        const u32 bTail = (u32)(lane & 7) * 144 + (u32)((lane >> 3) & 1) * 16;
#pragma unroll
        for (int ks = 0; ks < 4; ++ks) {
            u32 A[4];
            ldx4(A, aA + ks * 32);
#pragma unroll
            for (int tp = 0; tp < 6; ++tp) {
                u32 B[4];
                ldx4(B, sb + SM_W1H + tp * 16 * 144 + rowsel + ks * 32);
                mma16816(acc[2 * tp],     A, B);
                mma16816(acc[2 * tp + 1], A, B + 2);
                ldx4(B, sb + SM_W1L + tp * 16 * 144 + rowsel + ks * 32);
                mma16816(acc[2 * tp],     A, B);
                mma16816(acc[2 * tp + 1], A, B + 2);
            }
            {   // tail t = 12 (rows 96..103)
                u32 B[2];
                ldx2(B, sb + SM_W1H + 12 * 8 * 144 + bTail + ks * 32);
                mma16816(acc[12], A, B);
                ldx2(B, sb + SM_W1L + 12 * 8 * 144 + bTail + ks * 32);
                mma16816(acc[12], A, B);
            }
        }
    }

    // ---- epi2: direct float2 STG from accumulators ----
    {
        const int cb = 2 * (lane & 3);
        const size_t rb = (size_t)(n0 + 16 * w + (lane >> 2)) * 10000 + (size_t)m * 100;
#pragma unroll
        for (int t = 0; t < 13; ++t) {
            int c = 8 * t + cb;
            if (c < 100) {
                *(float2*)(out + rb + c)         = make_float2(acc[t][0], acc[t][1]);
                *(float2*)(out + rb + 80000 + c) = make_float2(acc[t][2], acc[t][3]);
            }
        }
    }
}

// ---------------------------------- launch -----------------------------------
extern "C" void kernel_launch(void* const* d_in, const int* in_sizes, int n_in,
                              void* d_out, int out_size) {
    const float* x;
    const float* ms_vs;
    if (in_sizes[0] == 2306) { ms_vs = (const float*)d_in[0]; x = (const float*)d_in[1]; }
    else                     { x = (const float*)d_in[0];     ms_vs = (const float*)d_in[1]; }
    float* out = (float*)d_out;

    u32 k0a, k0b, k1a, k1b;
    threefry(0u, 42u, 0u, 0u, k0a, k0b);
    threefry(0u, 42u, 0u, 1u, k1a, k1b);

    setup1_kernel<<<(E0 + E1 + TAILN + 255) / 256, 256>>>(ms_vs, out + OUT_PRED,
                                                          k0a, k0b, k1a, k1b);
    setup2_kernel<<<(S2TOT + 255) / 256, 256>>>(x);

    cudaFuncSetAttribute(pred_kernel, cudaFuncAttributeMaxDynamicSharedMemorySize, SM_BYTES);
    pred_kernel<<<dim3(NROWS / 128, NSAMP), 256, SM_BYTES>>>(out);
}

// round 16
// speedup vs baseline: 1.3116x; 1.0099x over previous
#include <cuda_runtime.h>
#include <cuda_fp16.h>
#include <cstdint>

// Problem constants
#define LEN_M   1088
#define MPRI    65
#define NSAMP   100
#define NROWS   16384
#define DD1     17
#define DH      64
#define OUT_PRED ((size_t)NROWS * NSAMP * NSAMP)

typedef unsigned long long u64;
typedef uint32_t u32;

// ---------------- device globals (scratch; no allocation allowed) ------------
__device__ float g_W0T[NSAMP * LEN_M];            // [m][j], j=k*64+h  (fp32)
__device__ float g_w1[MPRI * NSAMP];              // [d][c]            (fp32)
// fp16 hi/lo operand images (ldmatrix rows, padded strides, 16B aligned):
__device__ __align__(16) u32 g_ximgH[NROWS * 12];   // [n][16k], 48B stride
__device__ __align__(16) u32 g_ximgL[NROWS * 12];
__device__ __align__(16) u32 g_w0imgH[NSAMP * 64 * 12];  // [m][h][16k], 48B
__device__ __align__(16) u32 g_w0imgL[NSAMP * 64 * 12];
__device__ __align__(16) u32 g_w1imgH[104 * 36];    // [c][64k pad 72], 144B
__device__ __align__(16) float g_x16[NROWS];        // x[:,16] packed fp32
__device__ __align__(16) float g_w0k16[NSAMP * 64]; // W0[16][h] per m, fp32

// ---------------- Threefry2x32 (exact JAX rotation/key schedule) -------------
__host__ __device__ inline void threefry(u32 k0, u32 k1, u32 c0, u32 c1,
                                         u32& o0, u32& o1) {
    u32 ks2 = k0 ^ k1 ^ 0x1BD11BDAu;
    u32 x0 = c0 + k0, x1 = c1 + k1;
#define TF_ROUND(r) { x0 += x1; x1 = (x1 << (r)) | (x1 >> (32 - (r))); x1 ^= x0; }
    TF_ROUND(13) TF_ROUND(15) TF_ROUND(26) TF_ROUND(6)
    x0 += k1;  x1 += ks2 + 1u;
    TF_ROUND(17) TF_ROUND(29) TF_ROUND(16) TF_ROUND(24)
    x0 += ks2; x1 += k0 + 2u;
    TF_ROUND(13) TF_ROUND(15) TF_ROUND(26) TF_ROUND(6)
    x0 += k0;  x1 += k1 + 3u;
    TF_ROUND(17) TF_ROUND(29) TF_ROUND(16) TF_ROUND(24)
    x0 += k1;  x1 += ks2 + 4u;
    TF_ROUND(13) TF_ROUND(15) TF_ROUND(26) TF_ROUND(6)
    x0 += ks2; x1 += k0 + 5u;
#undef TF_ROUND
    o0 = x0; o1 = x1;
}

__device__ inline float erfinv_xla(float x) {
    float w = -log1pf(-x * x);
    float p;
    if (w < 5.0f) {
        w -= 2.5f;
        p = 2.81022636e-08f;
        p = fmaf(p, w, 3.43273939e-07f);
        p = fmaf(p, w, -3.5233877e-06f);
        p = fmaf(p, w, -4.39150654e-06f);
        p = fmaf(p, w, 0.00021858087f);
        p = fmaf(p, w, -0.00125372503f);
        p = fmaf(p, w, -0.00417768164f);
        p = fmaf(p, w, 0.246640727f);
        p = fmaf(p, w, 1.50140941f);
    } else {
        w = sqrtf(w) - 3.0f;
        p = -0.000200214257f;
        p = fmaf(p, w, 0.000100950558f);
        p = fmaf(p, w, 0.00134934322f);
        p = fmaf(p, w, -0.00367342844f);
        p = fmaf(p, w, 0.00573950773f);
        p = fmaf(p, w, -0.0076224613f);
        p = fmaf(p, w, 0.00943887047f);
        p = fmaf(p, w, 1.00167406f);
        p = fmaf(p, w, 2.83297682f);
    }
    return p * x;
}

__device__ inline float bits_to_normal(u32 bits) {
    float f = __uint_as_float((bits >> 9) | 0x3f800000u) - 1.0f;
    const float lo = -0.99999994f;
    float u = __fadd_rn(__fmul_rn(f, 2.0f), lo);
    u = fmaxf(lo, u);
    return 1.4142135381698608f * erfinv_xla(u);
}

// ---------------- setup1: sample weights (fp32) + output tail ----------------
#define E0 108800
#define E1 6500
#define TAILN 2306

__global__ void setup1_kernel(const float* __restrict__ ms_vs,
                              float* __restrict__ out_tail,
                              u32 k0a, u32 k0b, u32 k1a, u32 k1b) {
    int t = blockIdx.x * blockDim.x + threadIdx.x;
    if (t < E0) {
        u32 o0, o1;
        threefry(k0a, k0b, 0u, (u32)t, o0, o1);
        float n = bits_to_normal(o0 ^ o1);
        int j = t / 100, m = t - j * 100;
        float v = fabsf(ms_vs[1153 + j]) + 1e-6f;
        g_W0T[m * LEN_M + j] = fmaf(n, sqrtf(v), ms_vs[j]);
    } else if (t < E0 + E1) {
        int i = t - E0;
        u32 o0, o1;
        threefry(k1a, k1b, 0u, (u32)i, o0, o1);
        float n = bits_to_normal(o0 ^ o1);
        int d = i / 100, c = i - d * 100;
        float v = fabsf(ms_vs[2241 + d]) + 1e-6f;
        g_w1[d * 100 + c] = fmaf(n, sqrtf(v), ms_vs[1088 + d]);
    } else if (t < E0 + E1 + TAILN) {
        int q = t - E0 - E1;
        float val;
        if (q < 1088)       val = ms_vs[q];
        else if (q < 2176)  val = fabsf(ms_vs[1153 + (q - 1088)]) + 1e-6f;
        else if (q < 2241)  val = ms_vs[1088 + (q - 2176)];
        else                val = fabsf(ms_vs[q]) + 1e-6f;
        out_tail[q] = val;
    }
}

// ---------------- setup2: build fp16 hi/lo operand images --------------------
__device__ inline void f16split2(float a, float b, u32& H, u32& L) {
    half2 h = __floats2half2_rn(a, b);          // .x = a (low 16 bits)
    H = *(u32*)&h;
    float la = a - __half2float(__low2half(h));
    float lb = b - __half2float(__high2half(h));
    half2 l = __floats2half2_rn(la, lb);
    L = *(u32*)&l;
}

#define SX  131072   // X slots: 16384*8
#define SX1 16384    // x16
#define SW0 51200    // 100*64*8
#define SWK 6400     // w0k16
#define SW1 3744     // 104*36
#define S2TOT (SX + SX1 + SW0 + SWK + SW1)

__global__ void setup2_kernel(const float* __restrict__ x) {
    int s = blockIdx.x * blockDim.x + threadIdx.x;
    if (s < SX) {
        int n = s >> 3, p = s & 7;
        int k = 2 * p;
        float a = x[n * DD1 + k];
        float b = x[n * DD1 + k + 1];
        u32 H, L; f16split2(a, b, H, L);
        g_ximgH[n * 12 + p] = H;
        g_ximgL[n * 12 + p] = L;
    } else if (s < SX + SX1) {
        int n = s - SX;
        g_x16[n] = x[n * DD1 + 16];
    } else if (s < SX + SX1 + SW0) {
        int r = s - SX - SX1;
        int m = r >> 9, t = r & 511;
        int h = t >> 3, p = t & 7;
        int k = 2 * p;
        float a = g_W0T[m * LEN_M + k * DH + h];
        float b = g_W0T[m * LEN_M + (k + 1) * DH + h];
        u32 H, L; f16split2(a, b, H, L);
        g_w0imgH[(m * 64 + h) * 12 + p] = H;
        g_w0imgL[(m * 64 + h) * 12 + p] = L;
    } else if (s < SX + SX1 + SW0 + SWK) {
        int r = s - SX - SX1 - SW0;
        int m = r >> 6, h = r & 63;
        g_w0k16[r] = g_W0T[m * LEN_M + 16 * DH + h];
    } else if (s < S2TOT) {
        int r = s - SX - SX1 - SW0 - SWK;
        int c = r / 36, p = r - c * 36;
        int k = 2 * p;                            // K idx -> w1 row d=k+1
        float a = (k     < 64 && c < 100) ? g_w1[(k + 1) * 100 + c] : 0.0f;
        float b = (k + 1 < 64 && c < 100) ? g_w1[(k + 2) * 100 + c] : 0.0f;
        half2 h = __floats2half2_rn(a, b);
        g_w1imgH[r] = *(u32*)&h;
    }
}

// ---------------- mma.sync / ldmatrix / mbarrier helpers ---------------------
__device__ __forceinline__ void ldx4(u32* r, u32 addr) {
    asm volatile("ldmatrix.sync.aligned.m8n8.x4.shared.b16 {%0,%1,%2,%3}, [%4];"
                 : "=r"(r[0]), "=r"(r[1]), "=r"(r[2]), "=r"(r[3]) : "r"(addr));
}
__device__ __forceinline__ void ldx2(u32* r, u32 addr) {
    asm volatile("ldmatrix.sync.aligned.m8n8.x2.shared.b16 {%0,%1}, [%2];"
                 : "=r"(r[0]), "=r"(r[1]) : "r"(addr));
}
__device__ __forceinline__ void mma16816(float* d, const u32* a, const u32* b) {
    asm volatile("mma.sync.aligned.m16n8k16.row.col.f32.f16.f16.f32 "
                 "{%0,%1,%2,%3}, {%4,%5,%6,%7}, {%8,%9}, {%0,%1,%2,%3};"
                 : "+f"(d[0]), "+f"(d[1]), "+f"(d[2]), "+f"(d[3])
                 : "r"(a[0]), "r"(a[1]), "r"(a[2]), "r"(a[3]), "r"(b[0]), "r"(b[1]));
}
#define MBAR_INIT(a, n)   asm volatile("mbarrier.init.shared.b64 [%0], %1;" :: "r"(a), "r"((u32)(n)) : "memory")
#define MBAR_EXPECT(a, b) asm volatile("mbarrier.arrive.expect_tx.shared.b64 _, [%0], %1;" :: "r"(a), "r"((u32)(b)) : "memory")
__device__ __forceinline__ void mbar_wait(u32 addr, u32 parity) {
    asm volatile("{\n\t.reg .pred P1;\n\t"
        "WAIT_LOOP_%=:\n\t"
        "mbarrier.try_wait.parity.acquire.cta.shared::cta.b64 P1, [%0], %1, 0x989680;\n\t"
        "@P1 bra.uni WAIT_DONE_%=;\n\t"
        "bra.uni WAIT_LOOP_%=;\n\t"
        "WAIT_DONE_%=:\n\t}"
        :: "r"(addr), "r"(parity) : "memory");
}
__device__ __forceinline__ void bulk_cp(u32 dst_smem, const void* src, u32 bytes, u32 mbar) {
    asm volatile("cp.async.bulk.shared::cluster.global.mbarrier::complete_tx::bytes "
                 "[%0], [%1], %2, [%3];"
                 :: "r"(dst_smem), "l"(src), "r"(bytes), "r"(mbar) : "memory");
}

// ---------------- pred kernel ------------------------------------------------
// smem overlay layout (bytes):
//   [0..1024)       mbarrier/header
//   [1024..19456)   fill: XH(6144) XL(6144) W0H(3072) W0L(3072)
//                   later: ZH(18432) overlays this whole region exactly
//   [19456..20640)  X16(512) W0K(256) BS(416)
//   [20736..35712)  W1H(14976)
#define SM_XH   1024
#define SM_XL   7168
#define SM_W0H  13312
#define SM_W0L  16384
#define SM_X16  19456
#define SM_W0K  19968
#define SM_BS   20224
#define SM_W1H  20736
#define SM_ZH   1024      // overlays X/W0 after GEMM1
#define SM_BYTES 35712
#define FILL_BYTES 34576u

__global__ void __launch_bounds__(256, 4) pred_kernel(float* __restrict__ out) {
    extern __shared__ char sm[];
    u32 sb;
    asm("{ .reg .u64 t; cvta.to.shared.u64 t, %1; cvt.u32.u64 %0, t; }"
        : "=r"(sb) : "l"(sm));

    const int tid  = threadIdx.x;
    const int lane = tid & 31;
    const int w    = tid >> 5;              // 0..7: n-strip rows 16w..16w+15
    const int m    = blockIdx.y;
    const int n0   = blockIdx.x * 128;

    if (tid == 0) {
        MBAR_INIT(sb + 8, 1);
        MBAR_EXPECT(sb + 8, FILL_BYTES);
        bulk_cp(sb + SM_XH,  g_ximgH  + (size_t)n0 * 12, 6144u, sb + 8);
        bulk_cp(sb + SM_XL,  g_ximgL  + (size_t)n0 * 12, 6144u, sb + 8);
        bulk_cp(sb + SM_W0H, g_w0imgH + (size_t)m * 768, 3072u, sb + 8);
        bulk_cp(sb + SM_W0L, g_w0imgL + (size_t)m * 768, 3072u, sb + 8);
        bulk_cp(sb + SM_W1H, g_w1imgH, 14976u, sb + 8);
        bulk_cp(sb + SM_X16, g_x16 + n0, 512u, sb + 8);
        bulk_cp(sb + SM_W0K, g_w0k16 + m * 64, 256u, sb + 8);
        bulk_cp(sb + SM_BS,  g_w1, 400u, sb + 8);
    }
    __syncthreads();
    mbar_wait(sb + 8, 0);

    // ---- GEMM1: D1[16 rows x 64 h] per warp; K=16, 3-product fp16 split ----
    float acc1[8][4];
#pragma unroll
    for (int t = 0; t < 8; ++t)
#pragma unroll
        for (int j = 0; j < 4; ++j) acc1[t][j] = 0.0f;

    {
        u32 Ah[4], Al[4];
        ldx4(Ah, sb + SM_XH + (16 * w + (lane & 15)) * 48 + (lane >> 4) * 16);
        ldx4(Al, sb + SM_XL + (16 * w + (lane & 15)) * 48 + (lane >> 4) * 16);
        const u32 rowsel = (u32)(8 * (lane >> 4) + (lane & 7)) * 48 + (u32)((lane >> 3) & 1) * 16;
#pragma unroll
        for (int tp = 0; tp < 4; ++tp) {
            u32 B[4];
            ldx4(B, sb + SM_W0H + tp * 16 * 48 + rowsel);
            mma16816(acc1[2 * tp],     Ah, B);
            mma16816(acc1[2 * tp + 1], Ah, B + 2);
            u32 Bl[4];
            ldx4(Bl, sb + SM_W0L + tp * 16 * 48 + rowsel);
            mma16816(acc1[2 * tp],     Al, B);
            mma16816(acc1[2 * tp + 1], Al, B + 2);
            mma16816(acc1[2 * tp],     Ah, Bl);
            mma16816(acc1[2 * tp + 1], Ah, Bl + 2);
        }
    }
    __syncthreads();   // all warps done reading X/W0 before ZH overlays them

    // ---- epi1: + exact fp32 k=16 term, relu, fp16 round -> ZH smem ----
    {
        const int r0 = 16 * w + (lane >> 2);
        const int cb = 2 * (lane & 3);
        const float* x16s = (const float*)(sm + SM_X16);
        const float* w0ks = (const float*)(sm + SM_W0K);
        const float xa = x16s[r0], xb = x16s[r0 + 8];
#pragma unroll
        for (int t = 0; t < 8; ++t) {
            const float wa = w0ks[8 * t + cb], wb = w0ks[8 * t + cb + 1];
            float z0 = fmaxf(fmaf(xa, wa, acc1[t][0]), 0.0f);
            float z1 = fmaxf(fmaf(xa, wb, acc1[t][1]), 0.0f);
            half2 h01 = __floats2half2_rn(z0, z1);
            u32 off = r0 * 144 + (8 * t + cb) * 2;
            *(u32*)(sm + SM_ZH + off) = *(u32*)&h01;
            float z2 = fmaxf(fmaf(xb, wa, acc1[t][2]), 0.0f);
            float z3 = fmaxf(fmaf(xb, wb, acc1[t][3]), 0.0f);
            half2 h23 = __floats2half2_rn(z2, z3);
            off += 8 * 144;
            *(u32*)(sm + SM_ZH + off) = *(u32*)&h23;
        }
    }
    __syncthreads();

    // ---- GEMM2: D2[16 rows x 104 c] per warp; K=64; single product ----
    float acc[13][4];
    {
        const int cb = 2 * (lane & 3);
        const float* bs = (const float*)(sm + SM_BS);
#pragma unroll
        for (int t = 0; t < 13; ++t) {
            float b0 = bs[8 * t + cb], b1 = bs[8 * t + cb + 1];
            acc[t][0] = b0; acc[t][1] = b1; acc[t][2] = b0; acc[t][3] = b1;
        }
    }
    {
        const u32 aA = sb + SM_ZH + (16 * w + (lane & 15)) * 144 + (lane >> 4) * 16;
        const u32 rowsel = (u32)(8 * (lane >> 4) + (lane & 7)) * 144 + (u32)((lane >> 3) & 1) * 16;
        const u32 bTail = (u32)(lane & 7) * 144 + (u32)((lane >> 3) & 1) * 16;
#pragma unroll
        for (int ks = 0; ks < 4; ++ks) {
            u32 A[4];
            ldx4(A, aA + ks * 32);
#pragma unroll
            for (int tp = 0; tp < 6; ++tp) {
                u32 B[4];
                ldx4(B, sb + SM_W1H + tp * 16 * 144 + rowsel + ks * 32);
                mma16816(acc[2 * tp],     A, B);
                mma16816(acc[2 * tp + 1], A, B + 2);
            }
            {   // tail t = 12 (rows 96..103)
                u32 B[2];
                ldx2(B, sb + SM_W1H + 12 * 8 * 144 + bTail + ks * 32);
                mma16816(acc[12], A, B);
            }
        }
    }

    // ---- epi2: direct float2 STG from accumulators ----
    {
        const int cb = 2 * (lane & 3);
        const size_t rb = (size_t)(n0 + 16 * w + (lane >> 2)) * 10000 + (size_t)m * 100;
#pragma unroll
        for (int t = 0; t < 13; ++t) {
            int c = 8 * t + cb;
            if (c < 100) {
                *(float2*)(out + rb + c)         = make_float2(acc[t][0], acc[t][1]);
                *(float2*)(out + rb + 80000 + c) = make_float2(acc[t][2], acc[t][3]);
            }
        }
    }
}

// ---------------------------------- launch -----------------------------------
extern "C" void kernel_launch(void* const* d_in, const int* in_sizes, int n_in,
                              void* d_out, int out_size) {
    const float* x;
    const float* ms_vs;
    if (in_sizes[0] == 2306) { ms_vs = (const float*)d_in[0]; x = (const float*)d_in[1]; }
    else                     { x = (const float*)d_in[0];     ms_vs = (const float*)d_in[1]; }
    float* out = (float*)d_out;

    u32 k0a, k0b, k1a, k1b;
    threefry(0u, 42u, 0u, 0u, k0a, k0b);
    threefry(0u, 42u, 0u, 1u, k1a, k1b);

    setup1_kernel<<<(E0 + E1 + TAILN + 255) / 256, 256>>>(ms_vs, out + OUT_PRED,
                                                          k0a, k0b, k1a, k1b);
    setup2_kernel<<<(S2TOT + 255) / 256, 256>>>(x);

    cudaFuncSetAttribute(pred_kernel, cudaFuncAttributeMaxDynamicSharedMemorySize, SM_BYTES);
    pred_kernel<<<dim3(NROWS / 128, NSAMP), 256, SM_BYTES>>>(out);
}